// round 1
// baseline (speedup 1.0000x reference)
#include <cuda_runtime.h>

// AddDecomposedRelativePositions, SAM-style, fixed shapes:
// B=8, q_h=q_w=k_h=k_w=64, C=64, L=127 (no interpolation branch; rel idx = i-j+63)
//
// out[b, h*64+w, kh*64+kw] = attn[...] + rel_h[b,h,w,kh] + rel_w[b,h,w,kw]
//   rel_h[b,h,w,kh] = sum_c q[b,h,w,c] * rel_pos_h[h-kh+63, c]
//   rel_w[b,h,w,kw] = sum_c q[b,h,w,c] * rel_pos_w[w-kw+63, c]
//
// One CTA per (b,h): compute 64x64 rel_h and rel_w tiles in smem (tiny GEMM),
// then stream the CTA's contiguous 1MB attn slab with float4 ldcs/stcs.

#define THREADS 256

// smem layout (floats), phase 1 (staging, transposed c-major with bank padding):
//   q_t  [64][68]  : q_t[c*68 + w]   = q[b, h*64+w, c]
//   Rh_t [64][68]  : Rh_t[c*68 + kh] = rel_pos_h[h+63-kh, c]
//   Rw_t [64][132] : Rw_t[c*132 + i] = rel_pos_w[i, c]   (i in 0..126)
// phase 2 overlays the first 32KB:
//   relh [64][64], relw [64][64]
#define SMEM_FLOATS (64*68 + 64*68 + 64*132)   // 17152 floats = 68608 bytes

__global__ __launch_bounds__(THREADS, 2)
void addrelpos_kernel(const float* __restrict__ attn,
                      const float* __restrict__ q,
                      const float* __restrict__ rph,
                      const float* __restrict__ rpw,
                      float* __restrict__ out)
{
    extern __shared__ float smem[];
    float* q_t  = smem;                 // [64][68]
    float* Rh_t = smem + 64 * 68;       // [64][68]
    float* Rw_t = smem + 2 * 64 * 68;   // [64][132]

    const int t  = threadIdx.x;
    const int bx = blockIdx.x;          // bx = b*64 + h
    const int h  = bx & 63;

    // ---- Phase 1: stage operands (coalesced LDG, transposed STS) ----
    const float* qs = q + (size_t)bx * (64 * 64);   // q[b, h*64 + 0, 0]
    #pragma unroll 4
    for (int idx = t; idx < 64 * 64; idx += THREADS) {
        int c = idx & 63, w = idx >> 6;
        q_t[c * 68 + w] = qs[idx];
    }
    #pragma unroll 4
    for (int idx = t; idx < 64 * 64; idx += THREADS) {
        int c = idx & 63, kh = idx >> 6;
        Rh_t[c * 68 + kh] = rph[(h + 63 - kh) * 64 + c];
    }
    #pragma unroll 4
    for (int idx = t; idx < 127 * 64; idx += THREADS) {
        int c = idx & 63, i = idx >> 6;
        Rw_t[c * 132 + i] = rpw[idx];   // rpw[i*64 + c]
    }
    __syncthreads();

    // ---- Phase 2: 4x4 register-blocked mini-GEMMs ----
    // thread t owns w in [4*wb, 4*wb+4), kh/kw in [4*kb, 4*kb+4)
    const int wb = t >> 4;              // 0..15
    const int kb = t & 15;              // 0..15
    const int d0 = 4 * (wb - kb) + 60;  // 0..120; rel_w idx = d0 + 3 + jw - jk

    float aH[4][4] = {{0.f}}, aW[4][4] = {{0.f}};
    #pragma unroll 4
    for (int c = 0; c < 64; ++c) {
        float4 qv = *(const float4*)&q_t [c * 68  + 4 * wb];
        float4 rh = *(const float4*)&Rh_t[c * 68  + 4 * kb];
        float4 rA = *(const float4*)&Rw_t[c * 132 + d0];
        float4 rB = *(const float4*)&Rw_t[c * 132 + d0 + 4];
        float qa[4]  = {qv.x, qv.y, qv.z, qv.w};
        float rha[4] = {rh.x, rh.y, rh.z, rh.w};
        float rw8[8] = {rA.x, rA.y, rA.z, rA.w, rB.x, rB.y, rB.z, rB.w};
        #pragma unroll
        for (int j = 0; j < 4; ++j) {
            #pragma unroll
            for (int k = 0; k < 4; ++k) {
                aH[j][k] += qa[j] * rha[k];
                aW[j][k] += qa[j] * rw8[3 + j - k];
            }
        }
    }
    __syncthreads();   // phase-1 smem now dead; safe to overlay

    float* relh = smem;            // [64][64]
    float* relw = smem + 64 * 64;  // [64][64]
    #pragma unroll
    for (int j = 0; j < 4; ++j) {
        int w = 4 * wb + j;
        *(float4*)&relh[w * 64 + 4 * kb] = make_float4(aH[j][0], aH[j][1], aH[j][2], aH[j][3]);
        *(float4*)&relw[w * 64 + 4 * kb] = make_float4(aW[j][0], aW[j][1], aW[j][2], aW[j][3]);
    }
    __syncthreads();

    // ---- Phase 3: stream the contiguous 1MB attn slab for this (b,h) ----
    // element (w, kh, kw) at linear i = w*4096 + kh*64 + kw; float4 over kw.
    const size_t base = (size_t)bx * 262144;          // (b*4096 + h*64) * 4096
    const float4* a4 = (const float4*)(attn + base);
    float4*       o4 = (float4*)(out + base);

    #pragma unroll 4
    for (int i = t; i < 65536; i += THREADS) {
        int w   = i >> 10;
        int kh  = (i >> 4) & 63;
        int kw4 = i & 15;
        float4 a  = __ldcs(&a4[i]);
        float  rh = relh[w * 64 + kh];
        float4 rw = *(const float4*)&relw[w * 64 + kw4 * 4];
        float4 r;
        r.x = a.x + rh + rw.x;
        r.y = a.y + rh + rw.y;
        r.z = a.z + rh + rw.z;
        r.w = a.w + rh + rw.w;
        __stcs(&o4[i], r);
    }
}

extern "C" void kernel_launch(void* const* d_in, const int* in_sizes, int n_in,
                              void* d_out, int out_size)
{
    const float* attn = (const float*)d_in[0];
    const float* q    = (const float*)d_in[1];
    const float* rph  = (const float*)d_in[2];
    const float* rpw  = (const float*)d_in[3];
    float* out = (float*)d_out;

    const int B = in_sizes[0] / (4096 * 4096);   // 8 for the bench shapes

    cudaFuncSetAttribute(addrelpos_kernel,
                         cudaFuncAttributeMaxDynamicSharedMemorySize,
                         SMEM_FLOATS * sizeof(float));

    addrelpos_kernel<<<B * 64, THREADS, SMEM_FLOATS * sizeof(float)>>>(
        attn, q, rph, rpw, out);
}

// round 2
// speedup vs baseline: 1.7379x; 1.7379x over previous
#include <cuda_runtime.h>

// AddDecomposedRelativePositions, fixed bench shapes:
// B=8, q_h=q_w=k_h=k_w=64, C=64, L=127 (rel idx = i-j+63, no interpolation)
//
// Two-kernel split:
//   Kernel A: per (b,h) mini-GEMMs -> rel_h[b,h,w,kh], rel_w[b,h,w,kw] in
//             __device__ scratch (8MB each; stays L2-resident).
//   Kernel B: full-occupancy streaming add with batched LDG.128 (MLP=8),
//             evict-first on the 1GB attn/out stream, cached rel reads.

#define THREADS_A 256
#define SMEM_FLOATS (64*68 + 64*68 + 64*132)   // 17152 floats = 68608 bytes

// scratch for B<=8 (bench uses B=8): 8*64*64*64 floats = 2M floats = 8MB each
__device__ float g_relh[8 * 64 * 64 * 64];
__device__ float g_relw[8 * 64 * 64 * 64];

__global__ __launch_bounds__(THREADS_A, 2)
void relpos_gemm_kernel(const float* __restrict__ q,
                        const float* __restrict__ rph,
                        const float* __restrict__ rpw)
{
    extern __shared__ float smem[];
    float* q_t  = smem;                 // [64][68]  q_t[c*68+w]
    float* Rh_t = smem + 64 * 68;       // [64][68]  Rh_t[c*68+kh]
    float* Rw_t = smem + 2 * 64 * 68;   // [64][132] Rw_t[c*132+i]

    const int t  = threadIdx.x;
    const int bx = blockIdx.x;          // b*64 + h
    const int h  = bx & 63;

    // stage operands (coalesced LDG, transposed STS with bank padding)
    const float* qs = q + (size_t)bx * (64 * 64);
    #pragma unroll 4
    for (int idx = t; idx < 64 * 64; idx += THREADS_A) {
        int c = idx & 63, w = idx >> 6;
        q_t[c * 68 + w] = qs[idx];
    }
    #pragma unroll 4
    for (int idx = t; idx < 64 * 64; idx += THREADS_A) {
        int c = idx & 63, kh = idx >> 6;
        Rh_t[c * 68 + kh] = rph[(h + 63 - kh) * 64 + c];
    }
    #pragma unroll 4
    for (int idx = t; idx < 127 * 64; idx += THREADS_A) {
        int c = idx & 63, i = idx >> 6;
        Rw_t[c * 132 + i] = rpw[idx];
    }
    __syncthreads();

    // 4x4 register-blocked mini-GEMMs
    const int wb = t >> 4;              // 0..15
    const int kb = t & 15;              // 0..15
    const int d0 = 4 * (wb - kb) + 60;  // rel_w table offset

    float aH[4][4] = {{0.f}}, aW[4][4] = {{0.f}};
    #pragma unroll 4
    for (int c = 0; c < 64; ++c) {
        float4 qv = *(const float4*)&q_t [c * 68  + 4 * wb];
        float4 rh = *(const float4*)&Rh_t[c * 68  + 4 * kb];
        float4 rA = *(const float4*)&Rw_t[c * 132 + d0];
        float4 rB = *(const float4*)&Rw_t[c * 132 + d0 + 4];
        float qa[4]  = {qv.x, qv.y, qv.z, qv.w};
        float rha[4] = {rh.x, rh.y, rh.z, rh.w};
        float rw8[8] = {rA.x, rA.y, rA.z, rA.w, rB.x, rB.y, rB.z, rB.w};
        #pragma unroll
        for (int j = 0; j < 4; ++j) {
            #pragma unroll
            for (int k = 0; k < 4; ++k) {
                aH[j][k] += qa[j] * rha[k];
                aW[j][k] += qa[j] * rw8[3 + j - k];
            }
        }
    }

    // write rel tiles straight to global scratch (coalesced float4)
    float* rh_out = g_relh + (size_t)bx * 4096;   // [w][kh]
    float* rw_out = g_relw + (size_t)bx * 4096;   // [w][kw]
    #pragma unroll
    for (int j = 0; j < 4; ++j) {
        int w = 4 * wb + j;
        *(float4*)&rh_out[w * 64 + 4 * kb] = make_float4(aH[j][0], aH[j][1], aH[j][2], aH[j][3]);
        *(float4*)&rw_out[w * 64 + 4 * kb] = make_float4(aW[j][0], aW[j][1], aW[j][2], aW[j][3]);
    }
}

// ---- streaming add: out = attn + rel_h[..,kh] + rel_w[..,kw] ----
#define THREADS_B 256
#define GRID_B    2048
#define UB        8

__global__ __launch_bounds__(THREADS_B)
void stream_add_kernel(const float4* __restrict__ a4,
                       float4* __restrict__ o4,
                       int n4)
{
    const float*  relh  = g_relh;
    const float4* relw4 = (const float4*)g_relw;

    const int tid    = blockIdx.x * THREADS_B + threadIdx.x;
    const int stride = GRID_B * THREADS_B;          // 524288

    for (int base = tid; base < n4; base += stride * UB) {
        float4 a[UB];
        #pragma unroll
        for (int u = 0; u < UB; ++u) {
            int g = base + u * stride;
            if (g < n4) a[u] = __ldcs(&a4[g]);
        }
        #pragma unroll
        for (int u = 0; u < UB; ++u) {
            int g = base + u * stride;
            if (g < n4) {
                int bx  = g >> 16;          // (b,h) slab: 65536 float4 each
                int r   = g & 65535;
                int w   = r >> 10;
                int kh  = (r >> 4) & 63;
                int kw4 = r & 15;
                float  rh = __ldg(&relh [(bx << 12) + (w << 6) + kh]);
                float4 rw = __ldg(&relw4[(bx << 10) + (w << 4) + kw4]);
                float4 v  = a[u];
                v.x += rh + rw.x;
                v.y += rh + rw.y;
                v.z += rh + rw.z;
                v.w += rh + rw.w;
                __stcs(&o4[g], v);
            }
        }
    }
}

extern "C" void kernel_launch(void* const* d_in, const int* in_sizes, int n_in,
                              void* d_out, int out_size)
{
    const float* attn = (const float*)d_in[0];
    const float* q    = (const float*)d_in[1];
    const float* rph  = (const float*)d_in[2];
    const float* rpw  = (const float*)d_in[3];
    float* out = (float*)d_out;

    const int B = in_sizes[0] / (4096 * 4096);   // 8 on the bench

    cudaFuncSetAttribute(relpos_gemm_kernel,
                         cudaFuncAttributeMaxDynamicSharedMemorySize,
                         SMEM_FLOATS * sizeof(float));

    relpos_gemm_kernel<<<B * 64, THREADS_A, SMEM_FLOATS * sizeof(float)>>>(
        q, rph, rpw);

    const int n4 = in_sizes[0] / 4;              // total float4 elements
    stream_add_kernel<<<GRID_B, THREADS_B>>>(
        (const float4*)attn, (float4*)out, n4);
}

// round 3
// speedup vs baseline: 1.8721x; 1.0772x over previous
#include <cuda_runtime.h>

// AddDecomposedRelativePositions, fixed bench shapes:
// B=8, q_h=q_w=k_h=k_w=64, C=64, L=127 (rel idx = i-j+63, no interpolation)
//
// Kernel A: per (b,h) mini-GEMMs -> g_relh[bx][w][kh], g_relw[bx][w][kw]
//           (8MB each, L2-resident for kernel B).
// Kernel B: one CTA per (bx,w) row. rel_h/rel_w rows (512B) staged in smem,
//           then pure stream: 4x LDG.128 evict-first -> LDS -> 4x STG.128.

#define THREADS_A 256
#define SMEM_FLOATS (64*68 + 64*68 + 64*132)   // 68608 bytes

__device__ float g_relh[8 * 64 * 64 * 64];     // [bx][w][kh]
__device__ float g_relw[8 * 64 * 64 * 64];     // [bx][w][kw]

__global__ __launch_bounds__(THREADS_A, 2)
void relpos_gemm_kernel(const float* __restrict__ q,
                        const float* __restrict__ rph,
                        const float* __restrict__ rpw)
{
    extern __shared__ float smem[];
    float* q_t  = smem;                 // [64][68]  q_t[c*68+w]
    float* Rh_t = smem + 64 * 68;       // [64][68]  Rh_t[c*68+kh]
    float* Rw_t = smem + 2 * 64 * 68;   // [64][132] Rw_t[c*132+i]

    const int t  = threadIdx.x;
    const int bx = blockIdx.x;          // b*64 + h
    const int h  = bx & 63;

    const float* qs = q + (size_t)bx * (64 * 64);
    #pragma unroll 4
    for (int idx = t; idx < 64 * 64; idx += THREADS_A) {
        int c = idx & 63, w = idx >> 6;
        q_t[c * 68 + w] = qs[idx];
    }
    #pragma unroll 4
    for (int idx = t; idx < 64 * 64; idx += THREADS_A) {
        int c = idx & 63, kh = idx >> 6;
        Rh_t[c * 68 + kh] = rph[(h + 63 - kh) * 64 + c];
    }
    #pragma unroll 4
    for (int idx = t; idx < 127 * 64; idx += THREADS_A) {
        int c = idx & 63, i = idx >> 6;
        Rw_t[c * 132 + i] = rpw[idx];
    }
    __syncthreads();

    const int wb = t >> 4;              // 0..15
    const int kb = t & 15;              // 0..15
    const int d0 = 4 * (wb - kb) + 60;

    float aH[4][4] = {{0.f}}, aW[4][4] = {{0.f}};
    #pragma unroll 4
    for (int c = 0; c < 64; ++c) {
        float4 qv = *(const float4*)&q_t [c * 68  + 4 * wb];
        float4 rh = *(const float4*)&Rh_t[c * 68  + 4 * kb];
        float4 rA = *(const float4*)&Rw_t[c * 132 + d0];
        float4 rB = *(const float4*)&Rw_t[c * 132 + d0 + 4];
        float qa[4]  = {qv.x, qv.y, qv.z, qv.w};
        float rha[4] = {rh.x, rh.y, rh.z, rh.w};
        float rw8[8] = {rA.x, rA.y, rA.z, rA.w, rB.x, rB.y, rB.z, rB.w};
        #pragma unroll
        for (int j = 0; j < 4; ++j) {
            #pragma unroll
            for (int k = 0; k < 4; ++k) {
                aH[j][k] += qa[j] * rha[k];
                aW[j][k] += qa[j] * rw8[3 + j - k];
            }
        }
    }

    float* rh_out = g_relh + (size_t)bx * 4096;
    float* rw_out = g_relw + (size_t)bx * 4096;
    #pragma unroll
    for (int j = 0; j < 4; ++j) {
        int w = 4 * wb + j;
        *(float4*)&rh_out[w * 64 + 4 * kb] = make_float4(aH[j][0], aH[j][1], aH[j][2], aH[j][3]);
        *(float4*)&rw_out[w * 64 + 4 * kb] = make_float4(aW[j][0], aW[j][1], aW[j][2], aW[j][3]);
    }
}

// ---- Kernel B: one CTA per (bx, w) row; 1024 contiguous float4 each ----
#define THREADS_B 256

__global__ __launch_bounds__(THREADS_B)
void stream_add_kernel(const float4* __restrict__ a4,
                       float4* __restrict__ o4)
{
    __shared__ float4 rh4s[16];   // rel_h row: 64 floats
    __shared__ float4 rw4s[16];   // rel_w row: 64 floats (as 16 float4)

    const int t   = threadIdx.x;
    const int cta = blockIdx.x;               // bx*64 + w

    // stage rel rows (both contiguous, offset cta*64 floats = cta*16 float4)
    if (t < 16)
        rh4s[t] = __ldg(&((const float4*)g_relh)[cta * 16 + t]);
    else if (t >= 32 && t < 48)
        rw4s[t - 32] = __ldg(&((const float4*)g_relw)[cta * 16 + (t - 32)]);
    __syncthreads();

    const float* rhf = (const float*)rh4s;

    const float4* ap = a4 + (size_t)cta * 1024;
    float4*       op = o4 + (size_t)cta * 1024;

    // 4 front-batched streaming loads per thread
    float4 a[4];
    #pragma unroll
    for (int k = 0; k < 4; ++k)
        a[k] = __ldcs(&ap[t + 256 * k]);

    #pragma unroll
    for (int k = 0; k < 4; ++k) {
        int idx = t + 256 * k;
        int kh  = idx >> 4;        // 0..63
        int kw4 = idx & 15;        // 0..15
        float  rh = rhf[kh];
        float4 rw = rw4s[kw4];
        float4 v  = a[k];
        v.x += rh + rw.x;
        v.y += rh + rw.y;
        v.z += rh + rw.z;
        v.w += rh + rw.w;
        __stcs(&op[idx], v);
    }
}

extern "C" void kernel_launch(void* const* d_in, const int* in_sizes, int n_in,
                              void* d_out, int out_size)
{
    const float* attn = (const float*)d_in[0];
    const float* q    = (const float*)d_in[1];
    const float* rph  = (const float*)d_in[2];
    const float* rpw  = (const float*)d_in[3];
    float* out = (float*)d_out;

    const int B = in_sizes[0] / (4096 * 4096);   // 8 on the bench

    cudaFuncSetAttribute(relpos_gemm_kernel,
                         cudaFuncAttributeMaxDynamicSharedMemorySize,
                         SMEM_FLOATS * sizeof(float));

    relpos_gemm_kernel<<<B * 64, THREADS_A, SMEM_FLOATS * sizeof(float)>>>(
        q, rph, rpw);

    stream_add_kernel<<<B * 64 * 64, THREADS_B>>>(
        (const float4*)attn, (float4*)out);
}